// round 13
// baseline (speedup 1.0000x reference)
#include <cuda_runtime.h>
#include <cuda_fp16.h>
#include <cstdint>

// Problem dims (fixed): N=262144 rows, d_in=1024, d_hid=256, 128 bags.
#define NROWS_MAX 262144
#define DIN 1024
#define DHID 256
#define NEG_INF_F (__int_as_float(0xff800000))

__device__ __half         g_h16[(size_t)NROWS_MAX * DHID];   // 128 MB fp16 activations
__device__ float          g_scores[NROWS_MAX];
__device__ float          g_psum[4096 * 128];
__device__ float          g_psumsq[4096 * 128];
__device__ float          g_bn_a[DHID];
__device__ float          g_bn_c[DHID];
__device__ long long      g_off[1025];
__device__ unsigned short g_Bh[(size_t)DHID * DIN];          // W1^T fp16 [256][1024]

// ---------------- helpers ----------------
__device__ __forceinline__ uint32_t smem_u32(const void* p) {
    uint32_t a;
    asm("{ .reg .u64 t; cvta.to.shared.u64 t, %1; cvt.u32.u64 %0, t; }" : "=r"(a) : "l"(p));
    return a;
}
// fp16x2 pack, memory order: first, second
__device__ __forceinline__ uint32_t pack2h(float first, float second) {
    uint32_t r;
    asm("cvt.rn.f16x2.f32 %0, %1, %2;" : "=r"(r) : "f"(second), "f"(first));
    return r;
}
__device__ __forceinline__ void ldm4(uint32_t* r, uint32_t addr) {
    asm volatile("ldmatrix.sync.aligned.m8n8.x4.shared.b16 {%0,%1,%2,%3}, [%4];"
                 : "=r"(r[0]), "=r"(r[1]), "=r"(r[2]), "=r"(r[3]) : "r"(addr));
}
__device__ __forceinline__ void mma16816h(float* c, const uint32_t* a, uint32_t b0, uint32_t b1) {
    asm volatile(
        "mma.sync.aligned.m16n8k16.row.col.f32.f16.f16.f32 "
        "{%0,%1,%2,%3}, {%4,%5,%6,%7}, {%8,%9}, {%0,%1,%2,%3};"
        : "+f"(c[0]), "+f"(c[1]), "+f"(c[2]), "+f"(c[3])
        : "r"(a[0]), "r"(a[1]), "r"(a[2]), "r"(a[3]), "r"(b0), "r"(b1));
}
#define CP_ASYNC16(dst, src) \
    asm volatile("cp.async.ca.shared.global [%0], [%1], 16;" :: "r"(dst), "l"(src) : "memory")
#define CP_COMMIT()  asm volatile("cp.async.commit_group;" ::: "memory")
#define CP_WAIT0()   asm volatile("cp.async.wait_group 0;" ::: "memory")

// ---------------------------------------------------------------------------
// Kernel 0: W1 [1024][256] fp32 -> fp16, K-major [256][1024]
// ---------------------------------------------------------------------------
__global__ __launch_bounds__(256)
void convert_w1_kernel(const float* __restrict__ W1)
{
    const int n = blockIdx.x;
    const int t = threadIdx.x;
    #pragma unroll
    for (int i = 0; i < DIN / 256; ++i) {
        int k = t + 256 * i;
        float x = W1[(size_t)k * DHID + n];
        __half hh = __float2half_rn(x);
        g_Bh[(size_t)n * DIN + k] = *(unsigned short*)&hh;
    }
}

// ---------------------------------------------------------------------------
// Kernel 1: single-term fp16 mma.sync GEMM, KC=64, fp16 h output, fused stats.
// CTA 128m x 128n (grid (2, N/128)), 256 threads, 8 warps 4m x 2n, warp 32x64.
// Per-buffer: A 16KB (row r = 128B block r, 8 units, XOR (r&7) swizzle),
//             B 16KB same layout @ +16384. 2 buffers = 64KB -> 2 CTAs/SM.
// A prefetch split in two halves interleaved with ks-steps (reg pressure).
// ---------------------------------------------------------------------------
__global__ __launch_bounds__(256, 2)
void gemm_mma_kernel(const float* __restrict__ A, const float* __restrict__ b1, int nrows)
{
    extern __shared__ __align__(16) char sm[];
    __shared__ float sbias[128];

    const int tid  = threadIdx.x;
    const int wid  = tid >> 5;
    const int lane = tid & 31;
    const int n0   = blockIdx.x * 128;
    const int row0 = blockIdx.y * 128;

    const uint32_t smbase = smem_u32(sm);
    const int BUF = 32768;   // per-buffer: A 16KB @ +0, B 16KB @ +16384

    if (tid < 128) sbias[tid] = b1[n0 + tid];

    // ---- A staging: row = tid>>1, k-half = tid&1 (units ah*4 .. ah*4+3) ----
    const int arow  = tid >> 1;
    const int ahalf = tid & 1;
    const float* abase = A + (size_t)(row0 + arow) * DIN + ahalf * 32;
    uint32_t a_st[4];
    #pragma unroll
    for (int j = 0; j < 4; ++j)
        a_st[j] = (uint32_t)arow * 128 + (((ahalf * 4 + j) ^ (arow & 7)) << 4);

    // ---- B staging (cp.async): row = tid>>1, units (tid&1)*4 .. +3 ----
    const int bn    = tid >> 1;
    const int bhalf = tid & 1;
    const unsigned short* bp = g_Bh + (size_t)(n0 + bn) * DIN + bhalf * 32;
    uint32_t b_st[4];
    #pragma unroll
    for (int j = 0; j < 4; ++j)
        b_st[j] = 16384u + (uint32_t)bn * 128 + (((bhalf * 4 + j) ^ (bn & 7)) << 4);

    // ---- stage chunk 0 ----
    {
        #pragma unroll
        for (int j = 0; j < 4; ++j) CP_ASYNC16(smbase + b_st[j], bp + j * 8);
        CP_COMMIT();
        #pragma unroll
        for (int j = 0; j < 4; ++j) {
            float4 u = *(const float4*)(abase + j * 8);
            float4 v = *(const float4*)(abase + j * 8 + 4);
            *(uint4*)(sm + a_st[j]) = make_uint4(pack2h(u.x, u.y), pack2h(u.z, u.w),
                                                 pack2h(v.x, v.y), pack2h(v.z, v.w));
        }
        CP_WAIT0();
    }
    __syncthreads();

    const int m0w  = (wid & 3) * 32;
    const int n0w  = (wid >> 2) * 64;
    const int lr   = lane & 15;
    const int lsel = (lane >> 4) & 1;

    float acc[2][8][4];
    #pragma unroll
    for (int mt = 0; mt < 2; ++mt)
        #pragma unroll
        for (int nt = 0; nt < 8; ++nt)
            #pragma unroll
            for (int q = 0; q < 4; ++q) acc[mt][nt][q] = 0.f;

    const int NKC = DIN / 64;   // 16 chunks
    for (int kc = 0; kc < NKC; ++kc) {
        const uint32_t cur = (uint32_t)(kc & 1) * BUF;
        const bool pf = (kc + 1) < NKC;
        const uint32_t nxt = (uint32_t)((kc + 1) & 1) * BUF;
        const int ko = (kc + 1) * 64;

        float4 u0, v0, u1, v1;
        if (pf) {
            #pragma unroll
            for (int j = 0; j < 4; ++j) CP_ASYNC16(smbase + nxt + b_st[j], bp + ko + j * 8);
            CP_COMMIT();
            u0 = *(const float4*)(abase + ko);
            v0 = *(const float4*)(abase + ko + 4);
            u1 = *(const float4*)(abase + ko + 8);
            v1 = *(const float4*)(abase + ko + 12);
        }

        #pragma unroll
        for (int ks = 0; ks < 4; ++ks) {
            const uint32_t ku = (uint32_t)(2 * ks + lsel);   // 0..7
            uint32_t ah[2][4];
            #pragma unroll
            for (int mt = 0; mt < 2; ++mt) {
                int r = m0w + mt * 16 + lr;
                uint32_t addr = smbase + cur + (uint32_t)r * 128 + (((ku) ^ (r & 7)) << 4);
                ldm4(ah[mt], addr);
            }
            uint32_t bf[4][4];
            #pragma unroll
            for (int p = 0; p < 4; ++p) {
                int rn = n0w + p * 16 + lr;
                uint32_t addr = smbase + cur + 16384 + (uint32_t)rn * 128 + (((ku) ^ (rn & 7)) << 4);
                ldm4(bf[p], addr);
            }
            #pragma unroll
            for (int p = 0; p < 4; ++p)
                #pragma unroll
                for (int mt = 0; mt < 2; ++mt) {
                    mma16816h(acc[mt][2 * p],     ah[mt], bf[p][0], bf[p][2]);
                    mma16816h(acc[mt][2 * p + 1], ah[mt], bf[p][1], bf[p][3]);
                }

            // interleave A prefetch stores between ks-steps (two halves)
            if (pf && ks == 0) {
                *(uint4*)(sm + nxt + a_st[0]) = make_uint4(pack2h(u0.x, u0.y), pack2h(u0.z, u0.w),
                                                           pack2h(v0.x, v0.y), pack2h(v0.z, v0.w));
                *(uint4*)(sm + nxt + a_st[1]) = make_uint4(pack2h(u1.x, u1.y), pack2h(u1.z, u1.w),
                                                           pack2h(v1.x, v1.y), pack2h(v1.z, v1.w));
                u0 = *(const float4*)(abase + ko + 16);
                v0 = *(const float4*)(abase + ko + 20);
                u1 = *(const float4*)(abase + ko + 24);
                v1 = *(const float4*)(abase + ko + 28);
            }
            if (pf && ks == 2) {
                *(uint4*)(sm + nxt + a_st[2]) = make_uint4(pack2h(u0.x, u0.y), pack2h(u0.z, u0.w),
                                                           pack2h(v0.x, v0.y), pack2h(v0.z, v0.w));
                *(uint4*)(sm + nxt + a_st[3]) = make_uint4(pack2h(u1.x, u1.y), pack2h(u1.z, u1.w),
                                                           pack2h(v1.x, v1.y), pack2h(v1.z, v1.w));
            }
        }

        if (pf) CP_WAIT0();
        __syncthreads();
    }

    // ---- epilogue: bias add, write h fp16, fused column sum/sumsq ----
    const int erow = lane >> 2;
    const int ecol = (lane & 3) * 2;
    float* ss = (float*)sm;
    float* qq = (float*)(sm + 2048);
    #pragma unroll
    for (int nt = 0; nt < 8; ++nt) {
        int lc = n0w + nt * 8 + ecol;
        int gc = n0 + lc;
        float bx = sbias[lc], by = sbias[lc + 1];
        float sx = 0.f, sy = 0.f, qx = 0.f, qy = 0.f;
        #pragma unroll
        for (int mt = 0; mt < 2; ++mt) {
            int gr0 = row0 + m0w + mt * 16 + erow;
            float2 v0 = make_float2(acc[mt][nt][0] + bx, acc[mt][nt][1] + by);
            float2 v1 = make_float2(acc[mt][nt][2] + bx, acc[mt][nt][3] + by);
            *(uint32_t*)&g_h16[(size_t)gr0 * DHID + gc]       = pack2h(v0.x, v0.y);
            *(uint32_t*)&g_h16[(size_t)(gr0 + 8) * DHID + gc] = pack2h(v1.x, v1.y);
            sx += v0.x + v1.x;  sy += v0.y + v1.y;
            qx = fmaf(v0.x, v0.x, fmaf(v1.x, v1.x, qx));
            qy = fmaf(v0.y, v0.y, fmaf(v1.y, v1.y, qy));
        }
        #pragma unroll
        for (int o = 4; o < 32; o <<= 1) {
            sx += __shfl_xor_sync(0xffffffffu, sx, o);
            sy += __shfl_xor_sync(0xffffffffu, sy, o);
            qx += __shfl_xor_sync(0xffffffffu, qx, o);
            qy += __shfl_xor_sync(0xffffffffu, qy, o);
        }
        if (lane < 4) {
            int idx = ((wid * 8 + nt) * 4 + lane) * 2;
            ss[idx] = sx;  ss[idx + 1] = sy;
            qq[idx] = qx;  qq[idx + 1] = qy;
        }
    }
    __syncthreads();
    if (tid < 128) {
        const int lc = tid;
        const int hi = (lc >= 64);
        const int within = lc - hi * 64;
        const int nt  = within >> 3;
        const int grp = (within & 7) >> 1;
        const int xy  = within & 1;
        float s = 0.f, q = 0.f;
        #pragma unroll
        for (int w = 0; w < 4; ++w) {
            int wd = hi * 4 + w;
            int idx = ((wd * 8 + nt) * 4 + grp) * 2 + xy;
            s += ss[idx];
            q += qq[idx];
        }
        int cta = blockIdx.y * 2 + blockIdx.x;
        g_psum[cta * 128 + lc]   = s;
        g_psumsq[cta * 128 + lc] = q;
    }
}

// ---------------------------------------------------------------------------
// Kernel 3: finalize BN coefficients (256 blocks, tree reduce)
// ---------------------------------------------------------------------------
__global__ __launch_bounds__(256)
void stats_final_kernel(const float* __restrict__ gamma,
                        const float* __restrict__ beta, int nrows)
{
    __shared__ float rs[256], rq[256];
    const int c   = blockIdx.x;
    const int x   = c >> 7;
    const int lc  = c & 127;
    const int tid = threadIdx.x;
    float s = 0.f, q = 0.f;
    for (int y = tid; y < 2048; y += 256) {
        int cta = y * 2 + x;
        s += g_psum[cta * 128 + lc];
        q += g_psumsq[cta * 128 + lc];
    }
    rs[tid] = s; rq[tid] = q;
    __syncthreads();
    #pragma unroll
    for (int o = 128; o; o >>= 1) {
        if (tid < o) { rs[tid] += rs[tid + o]; rq[tid] += rq[tid + o]; }
        __syncthreads();
    }
    if (tid == 0) {
        float inv_n = 1.0f / (float)nrows;
        float mean  = rs[0] * inv_n;
        float var   = fmaf(-mean, mean, rq[0] * inv_n);
        float rstd  = rsqrtf(var + 1e-5f);
        float a     = gamma[c] * rstd;
        g_bn_a[c] = a;
        g_bn_c[c] = fmaf(-mean, a, beta[c]);
    }
}

// ---------------------------------------------------------------------------
// Kernel 4: scores (warp per row, fp16 h: one uint4 = 8 values per lane)
// ---------------------------------------------------------------------------
__global__ __launch_bounds__(256)
void scores_kernel(const float* __restrict__ W2, const float* __restrict__ b2,
                   int nrows)
{
    __shared__ float sa[DHID], sc[DHID], sw[DHID];
    const int tid = threadIdx.x;
    sa[tid] = g_bn_a[tid];
    sc[tid] = g_bn_c[tid];
    sw[tid] = W2[tid];
    __syncthreads();

    const int warp = tid >> 5;
    const int lane = tid & 31;
    const int row  = blockIdx.x * 8 + warp;
    if (row >= nrows) return;

    const int c0 = lane * 8;
    uint4 pk = *(const uint4*)(g_h16 + (size_t)row * DHID + c0);
    float acc = 0.f;
    const uint32_t* pw = &pk.x;
    #pragma unroll
    for (int j = 0; j < 4; ++j) {
        __half2 hv = *(__half2*)&pw[j];
        float2 v = __half22float2(hv);
        int c = c0 + 2 * j;
        acc += fmaxf(fmaf(sa[c],     v.x, sc[c]),     0.f) * sw[c];
        acc += fmaxf(fmaf(sa[c + 1], v.y, sc[c + 1]), 0.f) * sw[c + 1];
    }
    #pragma unroll
    for (int o = 16; o; o >>= 1) acc += __shfl_xor_sync(0xffffffffu, acc, o);
    if (lane == 0) g_scores[row] = acc + b2[0];
}

// Kernel 5: bag offsets
__global__ void offsets_kernel(const int* __restrict__ bag_sizes, int n_bags)
{
    if (threadIdx.x == 0 && blockIdx.x == 0) {
        long long a = 0;
        g_off[0] = 0;
        for (int b = 0; b < n_bags; ++b) { a += (long long)bag_sizes[b]; g_off[b + 1] = a; }
    }
}

// Kernel 6: per-bag stable softmax
__global__ __launch_bounds__(256)
void bag_softmax_kernel(float* __restrict__ out)
{
    __shared__ float red[256];
    const int b   = blockIdx.x;
    const int tid = threadIdx.x;
    const long long s = g_off[b];
    const long long e = g_off[b + 1];

    float m = NEG_INF_F;
    for (long long i = s + tid; i < e; i += 256) m = fmaxf(m, g_scores[i]);
    red[tid] = m;
    __syncthreads();
    #pragma unroll
    for (int o = 128; o; o >>= 1) {
        if (tid < o) red[tid] = fmaxf(red[tid], red[tid + o]);
        __syncthreads();
    }
    const float M = red[0];
    __syncthreads();

    float z = 0.f;
    for (long long i = s + tid; i < e; i += 256) {
        float ev = expf(g_scores[i] - M);
        out[i] = ev;
        z += ev;
    }
    red[tid] = z;
    __syncthreads();
    #pragma unroll
    for (int o = 128; o; o >>= 1) {
        if (tid < o) red[tid] += red[tid + o];
        __syncthreads();
    }
    const float inv = 1.0f / red[0];
    for (long long i = s + tid; i < e; i += 256) out[i] *= inv;
}

// ---------------------------------------------------------------------------
extern "C" void kernel_launch(void* const* d_in, const int* in_sizes, int n_in,
                              void* d_out, int out_size)
{
    const float* features  = (const float*)d_in[0];
    const int*   bag_sizes = (const int*)d_in[1];
    const float* W1        = (const float*)d_in[2];
    const float* b1        = (const float*)d_in[3];
    const float* gamma     = (const float*)d_in[4];
    const float* beta      = (const float*)d_in[5];
    const float* W2        = (const float*)d_in[6];
    const float* b2        = (const float*)d_in[7];
    float*       out       = (float*)d_out;

    const int n      = out_size;        // 262144
    const int n_bags = in_sizes[1];     // 128

    const int GEMM_SMEM = 65536;        // 2 x (16KB A + 16KB B)
    cudaFuncSetAttribute(gemm_mma_kernel,
                         cudaFuncAttributeMaxDynamicSharedMemorySize, GEMM_SMEM);

    convert_w1_kernel<<<DHID, 256>>>(W1);
    dim3 ggrid(2, n / 128);
    gemm_mma_kernel<<<ggrid, 256, GEMM_SMEM>>>(features, b1, n);
    stats_final_kernel<<<DHID, 256>>>(gamma, beta, n);
    scores_kernel<<<(n + 7) / 8, 256>>>(W2, b2, n);
    offsets_kernel<<<1, 1>>>(bag_sizes, n_bags);
    bag_softmax_kernel<<<n_bags, 256>>>(out);
}

// round 14
// speedup vs baseline: 1.4022x; 1.4022x over previous
#include <cuda_runtime.h>
#include <cuda_fp16.h>
#include <cstdint>

// Problem dims (fixed): N=262144 rows, d_in=1024, d_hid=256, 128 bags.
#define NROWS_MAX 262144
#define DIN 1024
#define DHID 256
#define NEG_INF_F (__int_as_float(0xff800000))

__device__ float          g_h[(size_t)NROWS_MAX * DHID];     // fp32 activations (R12)
__device__ float          g_scores[NROWS_MAX];
__device__ float          g_psum[2048 * 256];
__device__ float          g_psumsq[2048 * 256];
__device__ float          g_bn_a[DHID];
__device__ float          g_bn_c[DHID];
__device__ long long      g_off[1025];
__device__ unsigned short g_Bh[(size_t)DHID * DIN];          // W1^T fp16 [256][1024]

// ---------------- helpers ----------------
__device__ __forceinline__ uint32_t smem_u32(const void* p) {
    uint32_t a;
    asm("{ .reg .u64 t; cvta.to.shared.u64 t, %1; cvt.u32.u64 %0, t; }" : "=r"(a) : "l"(p));
    return a;
}
// fp16x2 pack, memory order: first, second
__device__ __forceinline__ uint32_t pack2h(float first, float second) {
    uint32_t r;
    asm("cvt.rn.f16x2.f32 %0, %1, %2;" : "=r"(r) : "f"(second), "f"(first));
    return r;
}
__device__ __forceinline__ void ldm4(uint32_t* r, uint32_t addr) {
    asm volatile("ldmatrix.sync.aligned.m8n8.x4.shared.b16 {%0,%1,%2,%3}, [%4];"
                 : "=r"(r[0]), "=r"(r[1]), "=r"(r[2]), "=r"(r[3]) : "r"(addr));
}
__device__ __forceinline__ void mma16816h(float* c, const uint32_t* a, uint32_t b0, uint32_t b1) {
    asm volatile(
        "mma.sync.aligned.m16n8k16.row.col.f32.f16.f16.f32 "
        "{%0,%1,%2,%3}, {%4,%5,%6,%7}, {%8,%9}, {%0,%1,%2,%3};"
        : "+f"(c[0]), "+f"(c[1]), "+f"(c[2]), "+f"(c[3])
        : "r"(a[0]), "r"(a[1]), "r"(a[2]), "r"(a[3]), "r"(b0), "r"(b1));
}
#define CP_ASYNC16(dst, src) \
    asm volatile("cp.async.ca.shared.global [%0], [%1], 16;" :: "r"(dst), "l"(src) : "memory")
#define CP_COMMIT()  asm volatile("cp.async.commit_group;" ::: "memory")
#define CP_WAIT0()   asm volatile("cp.async.wait_group 0;" ::: "memory")

// ---------------------------------------------------------------------------
// Kernel 0: W1 [1024][256] fp32 -> fp16, K-major [256][1024]
// ---------------------------------------------------------------------------
__global__ __launch_bounds__(256)
void convert_w1_kernel(const float* __restrict__ W1)
{
    const int n = blockIdx.x;
    const int t = threadIdx.x;
    #pragma unroll
    for (int i = 0; i < DIN / 256; ++i) {
        int k = t + 256 * i;
        float x = W1[(size_t)k * DHID + n];
        __half hh = __float2half_rn(x);
        g_Bh[(size_t)n * DIN + k] = *(unsigned short*)&hh;
    }
}

// ---------------------------------------------------------------------------
// Kernel 1: single-term fp16 mma.sync GEMM, KC=64, full-N CTA 128x256,
// 512 threads (16 warps 4m x 4n, warp 32x64), double-buffered, fused stats.
// Per-buffer: A 16KB (row r -> 128B block, XOR (r&7) unit swizzle),
//             B 32KB @ +16384 (same layout). 2 buffers = 96KB, 1 CTA/SM.
// Per-thread A prefetch = 16 floats (fits 128-reg budget; no spills).
// ---------------------------------------------------------------------------
__global__ __launch_bounds__(512, 1)
void gemm_mma_kernel(const float* __restrict__ A, const float* __restrict__ b1, int nrows)
{
    extern __shared__ __align__(16) char sm[];
    __shared__ float sbias[DHID];

    const int tid  = threadIdx.x;
    const int wid  = tid >> 5;
    const int lane = tid & 31;
    const int row0 = blockIdx.x * 128;

    const uint32_t smbase = smem_u32(sm);
    const int BUF = 49152;   // per-buffer: A 16KB @ +0, B 32KB @ +16384

    if (tid < 256) sbias[tid] = b1[tid];

    // ---- A staging: row = tid>>2 (4 threads/row), quarter q = tid&3 (16 cols) ----
    const int arow = tid >> 2;
    const int aq   = tid & 3;
    const float* abase = A + (size_t)(row0 + arow) * DIN + aq * 16;
    const uint32_t a_st0 = (uint32_t)arow * 128 + (((aq * 2    ) ^ (arow & 7)) << 4);
    const uint32_t a_st1 = (uint32_t)arow * 128 + (((aq * 2 + 1) ^ (arow & 7)) << 4);

    // ---- B staging (cp.async): row = tid>>1 (256 rows), half = tid&1 (units h*4..+3) ----
    const int bn    = tid >> 1;
    const int bhalf = tid & 1;
    const unsigned short* bp = g_Bh + (size_t)bn * DIN + bhalf * 32;
    uint32_t b_st[4];
    #pragma unroll
    for (int j = 0; j < 4; ++j)
        b_st[j] = 16384u + (uint32_t)bn * 128 + (((bhalf * 4 + j) ^ (bn & 7)) << 4);

    // ---- stage chunk 0 ----
    {
        #pragma unroll
        for (int j = 0; j < 4; ++j) CP_ASYNC16(smbase + b_st[j], bp + j * 8);
        CP_COMMIT();
        float4 u0 = *(const float4*)(abase);
        float4 v0 = *(const float4*)(abase + 4);
        float4 u1 = *(const float4*)(abase + 8);
        float4 v1 = *(const float4*)(abase + 12);
        *(uint4*)(sm + a_st0) = make_uint4(pack2h(u0.x, u0.y), pack2h(u0.z, u0.w),
                                           pack2h(v0.x, v0.y), pack2h(v0.z, v0.w));
        *(uint4*)(sm + a_st1) = make_uint4(pack2h(u1.x, u1.y), pack2h(u1.z, u1.w),
                                           pack2h(v1.x, v1.y), pack2h(v1.z, v1.w));
        CP_WAIT0();
    }
    __syncthreads();

    // ---- warp compute mapping: 4m x 4n ----
    const int m0w  = (wid >> 2) * 32;
    const int n0w  = (wid & 3) * 64;
    const int lr   = lane & 15;
    const int lsel = (lane >> 4) & 1;

    float acc[2][8][4];
    #pragma unroll
    for (int mt = 0; mt < 2; ++mt)
        #pragma unroll
        for (int nt = 0; nt < 8; ++nt)
            #pragma unroll
            for (int q = 0; q < 4; ++q) acc[mt][nt][q] = 0.f;

    const int NKC = DIN / 64;   // 16 chunks
    for (int kc = 0; kc < NKC; ++kc) {
        const uint32_t cur = (uint32_t)(kc & 1) * BUF;
        const bool pf = (kc + 1) < NKC;
        const uint32_t nxt = (uint32_t)((kc + 1) & 1) * BUF;
        const int ko = (kc + 1) * 64;

        float4 u0, v0, u1, v1;
        if (pf) {
            #pragma unroll
            for (int j = 0; j < 4; ++j) CP_ASYNC16(smbase + nxt + b_st[j], bp + ko + j * 8);
            CP_COMMIT();
            u0 = *(const float4*)(abase + ko);
            v0 = *(const float4*)(abase + ko + 4);
            u1 = *(const float4*)(abase + ko + 8);
            v1 = *(const float4*)(abase + ko + 12);
        }

        #pragma unroll
        for (int ks = 0; ks < 4; ++ks) {
            const uint32_t ku = (uint32_t)(2 * ks + lsel);   // 0..7
            uint32_t ah[2][4];
            #pragma unroll
            for (int mt = 0; mt < 2; ++mt) {
                int r = m0w + mt * 16 + lr;
                uint32_t addr = smbase + cur + (uint32_t)r * 128 + ((ku ^ (r & 7)) << 4);
                ldm4(ah[mt], addr);
            }
            uint32_t bf[4][4];
            #pragma unroll
            for (int p = 0; p < 4; ++p) {
                int rn = n0w + p * 16 + lr;
                uint32_t addr = smbase + cur + 16384 + (uint32_t)rn * 128 + ((ku ^ (rn & 7)) << 4);
                ldm4(bf[p], addr);
            }
            #pragma unroll
            for (int p = 0; p < 4; ++p)
                #pragma unroll
                for (int mt = 0; mt < 2; ++mt) {
                    mma16816h(acc[mt][2 * p],     ah[mt], bf[p][0], bf[p][2]);
                    mma16816h(acc[mt][2 * p + 1], ah[mt], bf[p][1], bf[p][3]);
                }
        }

        if (pf) {
            *(uint4*)(sm + nxt + a_st0) = make_uint4(pack2h(u0.x, u0.y), pack2h(u0.z, u0.w),
                                                     pack2h(v0.x, v0.y), pack2h(v0.z, v0.w));
            *(uint4*)(sm + nxt + a_st1) = make_uint4(pack2h(u1.x, u1.y), pack2h(u1.z, u1.w),
                                                     pack2h(v1.x, v1.y), pack2h(v1.z, v1.w));
            CP_WAIT0();
        }
        __syncthreads();
    }

    // ---- epilogue: bias add, write g_h (fp32), fused column sum/sumsq ----
    const int erow = lane >> 2;
    const int ecol = (lane & 3) * 2;
    float* ss = (float*)sm;                 // [16][8][4][2] = 1024 floats
    float* qq = (float*)(sm + 4096);
    #pragma unroll
    for (int nt = 0; nt < 8; ++nt) {
        int gc = n0w + nt * 8 + ecol;
        float bx = sbias[gc], by = sbias[gc + 1];
        float sx = 0.f, sy = 0.f, qx = 0.f, qy = 0.f;
        #pragma unroll
        for (int mt = 0; mt < 2; ++mt) {
            int gr0 = row0 + m0w + mt * 16 + erow;
            float2 v0 = make_float2(acc[mt][nt][0] + bx, acc[mt][nt][1] + by);
            float2 v1 = make_float2(acc[mt][nt][2] + bx, acc[mt][nt][3] + by);
            *(float2*)&g_h[(size_t)gr0 * DHID + gc]       = v0;
            *(float2*)&g_h[(size_t)(gr0 + 8) * DHID + gc] = v1;
            sx += v0.x + v1.x;  sy += v0.y + v1.y;
            qx = fmaf(v0.x, v0.x, fmaf(v1.x, v1.x, qx));
            qy = fmaf(v0.y, v0.y, fmaf(v1.y, v1.y, qy));
        }
        #pragma unroll
        for (int o = 4; o < 32; o <<= 1) {
            sx += __shfl_xor_sync(0xffffffffu, sx, o);
            sy += __shfl_xor_sync(0xffffffffu, sy, o);
            qx += __shfl_xor_sync(0xffffffffu, qx, o);
            qy += __shfl_xor_sync(0xffffffffu, qy, o);
        }
        if (lane < 4) {
            int idx = ((wid * 8 + nt) * 4 + lane) * 2;
            ss[idx] = sx;  ss[idx + 1] = sy;
            qq[idx] = qx;  qq[idx + 1] = qy;
        }
    }
    __syncthreads();
    if (tid < 256) {
        const int lc = tid;                 // global column
        const int nw = lc >> 6;
        const int within = lc & 63;
        const int nt  = within >> 3;
        const int grp = (within & 7) >> 1;
        const int xy  = within & 1;
        float s = 0.f, q = 0.f;
        #pragma unroll
        for (int mw = 0; mw < 4; ++mw) {
            int wd = mw * 4 + nw;
            int idx = ((wd * 8 + nt) * 4 + grp) * 2 + xy;
            s += ss[idx];
            q += qq[idx];
        }
        g_psum[(size_t)blockIdx.x * 256 + lc]   = s;
        g_psumsq[(size_t)blockIdx.x * 256 + lc] = q;
    }
}

// ---------------------------------------------------------------------------
// Kernel 3: finalize BN coefficients (256 blocks, tree reduce over 2048 CTAs)
// ---------------------------------------------------------------------------
__global__ __launch_bounds__(256)
void stats_final_kernel(const float* __restrict__ gamma,
                        const float* __restrict__ beta, int nrows)
{
    __shared__ float rs[256], rq[256];
    const int c   = blockIdx.x;
    const int tid = threadIdx.x;
    float s = 0.f, q = 0.f;
    for (int y = tid; y < 2048; y += 256) {
        s += g_psum[(size_t)y * 256 + c];
        q += g_psumsq[(size_t)y * 256 + c];
    }
    rs[tid] = s; rq[tid] = q;
    __syncthreads();
    #pragma unroll
    for (int o = 128; o; o >>= 1) {
        if (tid < o) { rs[tid] += rs[tid + o]; rq[tid] += rq[tid + o]; }
        __syncthreads();
    }
    if (tid == 0) {
        float inv_n = 1.0f / (float)nrows;
        float mean  = rs[0] * inv_n;
        float var   = fmaf(-mean, mean, rq[0] * inv_n);
        float rstd  = rsqrtf(var + 1e-5f);
        float a     = gamma[c] * rstd;
        g_bn_a[c] = a;
        g_bn_c[c] = fmaf(-mean, a, beta[c]);
    }
}

// Kernel 4: scores (warp per row, fp32 h — R12 verbatim)
__global__ __launch_bounds__(256)
void scores_kernel(const float* __restrict__ W2, const float* __restrict__ b2,
                   int nrows)
{
    __shared__ float sa[DHID], sc[DHID], sw[DHID];
    const int tid = threadIdx.x;
    sa[tid] = g_bn_a[tid];
    sc[tid] = g_bn_c[tid];
    sw[tid] = W2[tid];
    __syncthreads();

    const int warp = tid >> 5;
    const int lane = tid & 31;
    const int row  = blockIdx.x * 8 + warp;
    if (row >= nrows) return;

    const float* hr = g_h + (size_t)row * DHID;
    float acc = 0.f;
    #pragma unroll
    for (int part = 0; part < 2; ++part) {
        int c0 = part * 128 + lane * 4;
        float4 v = *(const float4*)(hr + c0);
        acc += fmaxf(fmaf(sa[c0 + 0], v.x, sc[c0 + 0]), 0.f) * sw[c0 + 0];
        acc += fmaxf(fmaf(sa[c0 + 1], v.y, sc[c0 + 1]), 0.f) * sw[c0 + 1];
        acc += fmaxf(fmaf(sa[c0 + 2], v.z, sc[c0 + 2]), 0.f) * sw[c0 + 2];
        acc += fmaxf(fmaf(sa[c0 + 3], v.w, sc[c0 + 3]), 0.f) * sw[c0 + 3];
    }
    #pragma unroll
    for (int o = 16; o; o >>= 1) acc += __shfl_xor_sync(0xffffffffu, acc, o);
    if (lane == 0) g_scores[row] = acc + b2[0];
}

// Kernel 5: bag offsets
__global__ void offsets_kernel(const int* __restrict__ bag_sizes, int n_bags)
{
    if (threadIdx.x == 0 && blockIdx.x == 0) {
        long long a = 0;
        g_off[0] = 0;
        for (int b = 0; b < n_bags; ++b) { a += (long long)bag_sizes[b]; g_off[b + 1] = a; }
    }
}

// Kernel 6: per-bag stable softmax
__global__ __launch_bounds__(256)
void bag_softmax_kernel(float* __restrict__ out)
{
    __shared__ float red[256];
    const int b   = blockIdx.x;
    const int tid = threadIdx.x;
    const long long s = g_off[b];
    const long long e = g_off[b + 1];

    float m = NEG_INF_F;
    for (long long i = s + tid; i < e; i += 256) m = fmaxf(m, g_scores[i]);
    red[tid] = m;
    __syncthreads();
    #pragma unroll
    for (int o = 128; o; o >>= 1) {
        if (tid < o) red[tid] = fmaxf(red[tid], red[tid + o]);
        __syncthreads();
    }
    const float M = red[0];
    __syncthreads();

    float z = 0.f;
    for (long long i = s + tid; i < e; i += 256) {
        float ev = expf(g_scores[i] - M);
        out[i] = ev;
        z += ev;
    }
    red[tid] = z;
    __syncthreads();
    #pragma unroll
    for (int o = 128; o; o >>= 1) {
        if (tid < o) red[tid] += red[tid + o];
        __syncthreads();
    }
    const float inv = 1.0f / red[0];
    for (long long i = s + tid; i < e; i += 256) out[i] *= inv;
}

// ---------------------------------------------------------------------------
extern "C" void kernel_launch(void* const* d_in, const int* in_sizes, int n_in,
                              void* d_out, int out_size)
{
    const float* features  = (const float*)d_in[0];
    const int*   bag_sizes = (const int*)d_in[1];
    const float* W1        = (const float*)d_in[2];
    const float* b1        = (const float*)d_in[3];
    const float* gamma     = (const float*)d_in[4];
    const float* beta      = (const float*)d_in[5];
    const float* W2        = (const float*)d_in[6];
    const float* b2        = (const float*)d_in[7];
    float*       out       = (float*)d_out;

    const int n      = out_size;        // 262144
    const int n_bags = in_sizes[1];     // 128

    const int GEMM_SMEM = 98304;        // 2 x (16KB A + 32KB B)
    cudaFuncSetAttribute(gemm_mma_kernel,
                         cudaFuncAttributeMaxDynamicSharedMemorySize, GEMM_SMEM);

    convert_w1_kernel<<<DHID, 256>>>(W1);
    gemm_mma_kernel<<<n / 128, 512, GEMM_SMEM>>>(features, b1, n);
    stats_final_kernel<<<DHID, 256>>>(gamma, beta, n);
    scores_kernel<<<(n + 7) / 8, 256>>>(W2, b2, n);
    offsets_kernel<<<1, 1>>>(bag_sizes, n_bags);
    bag_softmax_kernel<<<n_bags, 256>>>(out);
}

// round 15
// speedup vs baseline: 1.4505x; 1.0345x over previous
#include <cuda_runtime.h>
#include <cuda_fp16.h>
#include <cstdint>

// Problem dims (fixed): N=262144 rows, d_in=1024, d_hid=256, 128 bags.
#define NROWS_MAX 262144
#define DIN 1024
#define DHID 256
#define NEG_INF_F (__int_as_float(0xff800000))

__device__ __half         g_h16[(size_t)NROWS_MAX * DHID];   // 128 MB fp16 activations
__device__ float          g_scores[NROWS_MAX];
__device__ float          g_psum[2048 * 256];
__device__ float          g_psumsq[2048 * 256];
__device__ float          g_bn_a[DHID];
__device__ float          g_bn_c[DHID];
__device__ long long      g_off[1025];
__device__ unsigned short g_Bh[(size_t)DHID * DIN];          // W1^T fp16 [256][1024]

// ---------------- helpers ----------------
__device__ __forceinline__ uint32_t smem_u32(const void* p) {
    uint32_t a;
    asm("{ .reg .u64 t; cvta.to.shared.u64 t, %1; cvt.u32.u64 %0, t; }" : "=r"(a) : "l"(p));
    return a;
}
// fp16x2 pack, memory order: first, second
__device__ __forceinline__ uint32_t pack2h(float first, float second) {
    uint32_t r;
    asm("cvt.rn.f16x2.f32 %0, %1, %2;" : "=r"(r) : "f"(second), "f"(first));
    return r;
}
__device__ __forceinline__ void ldm4(uint32_t* r, uint32_t addr) {
    asm volatile("ldmatrix.sync.aligned.m8n8.x4.shared.b16 {%0,%1,%2,%3}, [%4];"
                 : "=r"(r[0]), "=r"(r[1]), "=r"(r[2]), "=r"(r[3]) : "r"(addr));
}
__device__ __forceinline__ void mma16816h(float* c, const uint32_t* a, uint32_t b0, uint32_t b1) {
    asm volatile(
        "mma.sync.aligned.m16n8k16.row.col.f32.f16.f16.f32 "
        "{%0,%1,%2,%3}, {%4,%5,%6,%7}, {%8,%9}, {%0,%1,%2,%3};"
        : "+f"(c[0]), "+f"(c[1]), "+f"(c[2]), "+f"(c[3])
        : "r"(a[0]), "r"(a[1]), "r"(a[2]), "r"(a[3]), "r"(b0), "r"(b1));
}
#define CP_ASYNC16(dst, src) \
    asm volatile("cp.async.ca.shared.global [%0], [%1], 16;" :: "r"(dst), "l"(src) : "memory")
#define CP_COMMIT()  asm volatile("cp.async.commit_group;" ::: "memory")
#define CP_WAIT0()   asm volatile("cp.async.wait_group 0;" ::: "memory")

// ---------------------------------------------------------------------------
// Kernel 0: W1 [1024][256] fp32 -> fp16, K-major [256][1024]
// ---------------------------------------------------------------------------
__global__ __launch_bounds__(256)
void convert_w1_kernel(const float* __restrict__ W1)
{
    const int n = blockIdx.x;
    const int t = threadIdx.x;
    #pragma unroll
    for (int i = 0; i < DIN / 256; ++i) {
        int k = t + 256 * i;
        float x = W1[(size_t)k * DHID + n];
        __half hh = __float2half_rn(x);
        g_Bh[(size_t)n * DIN + k] = *(unsigned short*)&hh;
    }
}

// ---------------------------------------------------------------------------
// Kernel 1: single-term fp16 mma.sync GEMM, KC=64, full-N CTA 128x256,
// 512 threads (16 warps 4m x 4n, warp 32x64), double-buffered, fused stats.
// Identical to R14 except the h output is fp16 (halved epilogue traffic).
// ---------------------------------------------------------------------------
__global__ __launch_bounds__(512, 1)
void gemm_mma_kernel(const float* __restrict__ A, const float* __restrict__ b1, int nrows)
{
    extern __shared__ __align__(16) char sm[];
    __shared__ float sbias[DHID];

    const int tid  = threadIdx.x;
    const int wid  = tid >> 5;
    const int lane = tid & 31;
    const int row0 = blockIdx.x * 128;

    const uint32_t smbase = smem_u32(sm);
    const int BUF = 49152;   // per-buffer: A 16KB @ +0, B 32KB @ +16384

    if (tid < 256) sbias[tid] = b1[tid];

    // ---- A staging: row = tid>>2 (4 threads/row), quarter q = tid&3 (16 cols) ----
    const int arow = tid >> 2;
    const int aq   = tid & 3;
    const float* abase = A + (size_t)(row0 + arow) * DIN + aq * 16;
    const uint32_t a_st0 = (uint32_t)arow * 128 + (((aq * 2    ) ^ (arow & 7)) << 4);
    const uint32_t a_st1 = (uint32_t)arow * 128 + (((aq * 2 + 1) ^ (arow & 7)) << 4);

    // ---- B staging (cp.async): row = tid>>1 (256 rows), half = tid&1 ----
    const int bn    = tid >> 1;
    const int bhalf = tid & 1;
    const unsigned short* bp = g_Bh + (size_t)bn * DIN + bhalf * 32;
    uint32_t b_st[4];
    #pragma unroll
    for (int j = 0; j < 4; ++j)
        b_st[j] = 16384u + (uint32_t)bn * 128 + (((bhalf * 4 + j) ^ (bn & 7)) << 4);

    // ---- stage chunk 0 ----
    {
        #pragma unroll
        for (int j = 0; j < 4; ++j) CP_ASYNC16(smbase + b_st[j], bp + j * 8);
        CP_COMMIT();
        float4 u0 = *(const float4*)(abase);
        float4 v0 = *(const float4*)(abase + 4);
        float4 u1 = *(const float4*)(abase + 8);
        float4 v1 = *(const float4*)(abase + 12);
        *(uint4*)(sm + a_st0) = make_uint4(pack2h(u0.x, u0.y), pack2h(u0.z, u0.w),
                                           pack2h(v0.x, v0.y), pack2h(v0.z, v0.w));
        *(uint4*)(sm + a_st1) = make_uint4(pack2h(u1.x, u1.y), pack2h(u1.z, u1.w),
                                           pack2h(v1.x, v1.y), pack2h(v1.z, v1.w));
        CP_WAIT0();
    }
    __syncthreads();

    // ---- warp compute mapping: 4m x 4n ----
    const int m0w  = (wid >> 2) * 32;
    const int n0w  = (wid & 3) * 64;
    const int lr   = lane & 15;
    const int lsel = (lane >> 4) & 1;

    float acc[2][8][4];
    #pragma unroll
    for (int mt = 0; mt < 2; ++mt)
        #pragma unroll
        for (int nt = 0; nt < 8; ++nt)
            #pragma unroll
            for (int q = 0; q < 4; ++q) acc[mt][nt][q] = 0.f;

    const int NKC = DIN / 64;   // 16 chunks
    for (int kc = 0; kc < NKC; ++kc) {
        const uint32_t cur = (uint32_t)(kc & 1) * BUF;
        const bool pf = (kc + 1) < NKC;
        const uint32_t nxt = (uint32_t)((kc + 1) & 1) * BUF;
        const int ko = (kc + 1) * 64;

        float4 u0, v0, u1, v1;
        if (pf) {
            #pragma unroll
            for (int j = 0; j < 4; ++j) CP_ASYNC16(smbase + nxt + b_st[j], bp + ko + j * 8);
            CP_COMMIT();
            u0 = *(const float4*)(abase + ko);
            v0 = *(const float4*)(abase + ko + 4);
            u1 = *(const float4*)(abase + ko + 8);
            v1 = *(const float4*)(abase + ko + 12);
        }

        #pragma unroll
        for (int ks = 0; ks < 4; ++ks) {
            const uint32_t ku = (uint32_t)(2 * ks + lsel);   // 0..7
            uint32_t ah[2][4];
            #pragma unroll
            for (int mt = 0; mt < 2; ++mt) {
                int r = m0w + mt * 16 + lr;
                uint32_t addr = smbase + cur + (uint32_t)r * 128 + ((ku ^ (r & 7)) << 4);
                ldm4(ah[mt], addr);
            }
            uint32_t bf[4][4];
            #pragma unroll
            for (int p = 0; p < 4; ++p) {
                int rn = n0w + p * 16 + lr;
                uint32_t addr = smbase + cur + 16384 + (uint32_t)rn * 128 + ((ku ^ (rn & 7)) << 4);
                ldm4(bf[p], addr);
            }
            #pragma unroll
            for (int p = 0; p < 4; ++p)
                #pragma unroll
                for (int mt = 0; mt < 2; ++mt) {
                    mma16816h(acc[mt][2 * p],     ah[mt], bf[p][0], bf[p][2]);
                    mma16816h(acc[mt][2 * p + 1], ah[mt], bf[p][1], bf[p][3]);
                }
        }

        if (pf) {
            *(uint4*)(sm + nxt + a_st0) = make_uint4(pack2h(u0.x, u0.y), pack2h(u0.z, u0.w),
                                                     pack2h(v0.x, v0.y), pack2h(v0.z, v0.w));
            *(uint4*)(sm + nxt + a_st1) = make_uint4(pack2h(u1.x, u1.y), pack2h(u1.z, u1.w),
                                                     pack2h(v1.x, v1.y), pack2h(v1.z, v1.w));
            CP_WAIT0();
        }
        __syncthreads();
    }

    // ---- epilogue: bias add, write h fp16, fused column sum/sumsq ----
    const int erow = lane >> 2;
    const int ecol = (lane & 3) * 2;
    float* ss = (float*)sm;                 // [16][8][4][2] = 1024 floats
    float* qq = (float*)(sm + 4096);
    #pragma unroll
    for (int nt = 0; nt < 8; ++nt) {
        int gc = n0w + nt * 8 + ecol;
        float bx = sbias[gc], by = sbias[gc + 1];
        float sx = 0.f, sy = 0.f, qx = 0.f, qy = 0.f;
        #pragma unroll
        for (int mt = 0; mt < 2; ++mt) {
            int gr0 = row0 + m0w + mt * 16 + erow;
            float2 v0 = make_float2(acc[mt][nt][0] + bx, acc[mt][nt][1] + by);
            float2 v1 = make_float2(acc[mt][nt][2] + bx, acc[mt][nt][3] + by);
            *(uint32_t*)&g_h16[(size_t)gr0 * DHID + gc]       = pack2h(v0.x, v0.y);
            *(uint32_t*)&g_h16[(size_t)(gr0 + 8) * DHID + gc] = pack2h(v1.x, v1.y);
            sx += v0.x + v1.x;  sy += v0.y + v1.y;
            qx = fmaf(v0.x, v0.x, fmaf(v1.x, v1.x, qx));
            qy = fmaf(v0.y, v0.y, fmaf(v1.y, v1.y, qy));
        }
        #pragma unroll
        for (int o = 4; o < 32; o <<= 1) {
            sx += __shfl_xor_sync(0xffffffffu, sx, o);
            sy += __shfl_xor_sync(0xffffffffu, sy, o);
            qx += __shfl_xor_sync(0xffffffffu, qx, o);
            qy += __shfl_xor_sync(0xffffffffu, qy, o);
        }
        if (lane < 4) {
            int idx = ((wid * 8 + nt) * 4 + lane) * 2;
            ss[idx] = sx;  ss[idx + 1] = sy;
            qq[idx] = qx;  qq[idx + 1] = qy;
        }
    }
    __syncthreads();
    if (tid < 256) {
        const int lc = tid;
        const int nw = lc >> 6;
        const int within = lc & 63;
        const int nt  = within >> 3;
        const int grp = (within & 7) >> 1;
        const int xy  = within & 1;
        float s = 0.f, q = 0.f;
        #pragma unroll
        for (int mw = 0; mw < 4; ++mw) {
            int wd = mw * 4 + nw;
            int idx = ((wd * 8 + nt) * 4 + grp) * 2 + xy;
            s += ss[idx];
            q += qq[idx];
        }
        g_psum[(size_t)blockIdx.x * 256 + lc]   = s;
        g_psumsq[(size_t)blockIdx.x * 256 + lc] = q;
    }
}

// ---------------------------------------------------------------------------
// Kernel 3: finalize BN coefficients (256 blocks, tree reduce over 2048 CTAs)
// ---------------------------------------------------------------------------
__global__ __launch_bounds__(256)
void stats_final_kernel(const float* __restrict__ gamma,
                        const float* __restrict__ beta, int nrows)
{
    __shared__ float rs[256], rq[256];
    const int c   = blockIdx.x;
    const int tid = threadIdx.x;
    float s = 0.f, q = 0.f;
    for (int y = tid; y < 2048; y += 256) {
        s += g_psum[(size_t)y * 256 + c];
        q += g_psumsq[(size_t)y * 256 + c];
    }
    rs[tid] = s; rq[tid] = q;
    __syncthreads();
    #pragma unroll
    for (int o = 128; o; o >>= 1) {
        if (tid < o) { rs[tid] += rs[tid + o]; rq[tid] += rq[tid + o]; }
        __syncthreads();
    }
    if (tid == 0) {
        float inv_n = 1.0f / (float)nrows;
        float mean  = rs[0] * inv_n;
        float var   = fmaf(-mean, mean, rq[0] * inv_n);
        float rstd  = rsqrtf(var + 1e-5f);
        float a     = gamma[c] * rstd;
        g_bn_a[c] = a;
        g_bn_c[c] = fmaf(-mean, a, beta[c]);
    }
}

// ---------------------------------------------------------------------------
// Kernel 4: scores, fp16 h. 2 rows per warp, both 16B loads issued together
// (2x MLP vs R13's 1-row variant that was latency-bound at 66us).
// ---------------------------------------------------------------------------
__global__ __launch_bounds__(256)
void scores_kernel(const float* __restrict__ W2, const float* __restrict__ b2,
                   int nrows)
{
    __shared__ float sa[DHID], sc[DHID], sw[DHID];
    const int tid = threadIdx.x;
    sa[tid] = g_bn_a[tid];
    sc[tid] = g_bn_c[tid];
    sw[tid] = W2[tid];
    __syncthreads();

    const int warp = tid >> 5;
    const int lane = tid & 31;
    const int row0 = blockIdx.x * 16 + warp * 2;
    if (row0 >= nrows) return;

    const int c0 = lane * 8;
    uint4 p0 = *(const uint4*)(g_h16 + (size_t)row0 * DHID + c0);
    uint4 p1 = *(const uint4*)(g_h16 + (size_t)(row0 + 1) * DHID + c0);

    float acc0 = 0.f, acc1 = 0.f;
    const uint32_t* w0 = &p0.x;
    const uint32_t* w1 = &p1.x;
    #pragma unroll
    for (int j = 0; j < 4; ++j) {
        int c = c0 + 2 * j;
        float2 v0 = __half22float2(*(__half2*)&w0[j]);
        float2 v1 = __half22float2(*(__half2*)&w1[j]);
        float a0 = sa[c], a1 = sa[c + 1];
        float cc0 = sc[c], cc1 = sc[c + 1];
        float ww0 = sw[c], ww1 = sw[c + 1];
        acc0 += fmaxf(fmaf(a0, v0.x, cc0), 0.f) * ww0;
        acc1 += fmaxf(fmaf(a0, v1.x, cc0), 0.f) * ww0;
        acc0 += fmaxf(fmaf(a1, v0.y, cc1), 0.f) * ww1;
        acc1 += fmaxf(fmaf(a1, v1.y, cc1), 0.f) * ww1;
    }
    #pragma unroll
    for (int o = 16; o; o >>= 1) {
        acc0 += __shfl_xor_sync(0xffffffffu, acc0, o);
        acc1 += __shfl_xor_sync(0xffffffffu, acc1, o);
    }
    if (lane == 0) {
        float bb = b2[0];
        g_scores[row0]     = acc0 + bb;
        g_scores[row0 + 1] = acc1 + bb;
    }
}

// Kernel 5: bag offsets
__global__ void offsets_kernel(const int* __restrict__ bag_sizes, int n_bags)
{
    if (threadIdx.x == 0 && blockIdx.x == 0) {
        long long a = 0;
        g_off[0] = 0;
        for (int b = 0; b < n_bags; ++b) { a += (long long)bag_sizes[b]; g_off[b + 1] = a; }
    }
}

// Kernel 6: per-bag stable softmax
__global__ __launch_bounds__(256)
void bag_softmax_kernel(float* __restrict__ out)
{
    __shared__ float red[256];
    const int b   = blockIdx.x;
    const int tid = threadIdx.x;
    const long long s = g_off[b];
    const long long e = g_off[b + 1];

    float m = NEG_INF_F;
    for (long long i = s + tid; i < e; i += 256) m = fmaxf(m, g_scores[i]);
    red[tid] = m;
    __syncthreads();
    #pragma unroll
    for (int o = 128; o; o >>= 1) {
        if (tid < o) red[tid] = fmaxf(red[tid], red[tid + o]);
        __syncthreads();
    }
    const float M = red[0];
    __syncthreads();

    float z = 0.f;
    for (long long i = s + tid; i < e; i += 256) {
        float ev = expf(g_scores[i] - M);
        out[i] = ev;
        z += ev;
    }
    red[tid] = z;
    __syncthreads();
    #pragma unroll
    for (int o = 128; o; o >>= 1) {
        if (tid < o) red[tid] += red[tid + o];
        __syncthreads();
    }
    const float inv = 1.0f / red[0];
    for (long long i = s + tid; i < e; i += 256) out[i] *= inv;
}

// ---------------------------------------------------------------------------
extern "C" void kernel_launch(void* const* d_in, const int* in_sizes, int n_in,
                              void* d_out, int out_size)
{
    const float* features  = (const float*)d_in[0];
    const int*   bag_sizes = (const int*)d_in[1];
    const float* W1        = (const float*)d_in[2];
    const float* b1        = (const float*)d_in[3];
    const float* gamma     = (const float*)d_in[4];
    const float* beta      = (const float*)d_in[5];
    const float* W2        = (const float*)d_in[6];
    const float* b2        = (const float*)d_in[7];
    float*       out       = (float*)d_out;

    const int n      = out_size;        // 262144
    const int n_bags = in_sizes[1];     // 128

    const int GEMM_SMEM = 98304;        // 2 x (16KB A + 32KB B)
    cudaFuncSetAttribute(gemm_mma_kernel,
                         cudaFuncAttributeMaxDynamicSharedMemorySize, GEMM_SMEM);

    convert_w1_kernel<<<DHID, 256>>>(W1);
    gemm_mma_kernel<<<n / 128, 512, GEMM_SMEM>>>(features, b1, n);
    stats_final_kernel<<<DHID, 256>>>(gamma, beta, n);
    scores_kernel<<<(n + 15) / 16, 256>>>(W2, b2, n);
    offsets_kernel<<<1, 1>>>(bag_sizes, n_bags);
    bag_softmax_kernel<<<n_bags, 256>>>(out);
}

// round 16
// speedup vs baseline: 1.4877x; 1.0256x over previous
#include <cuda_runtime.h>
#include <cuda_fp16.h>
#include <cstdint>

// Problem dims (fixed): N=262144 rows, d_in=1024, d_hid=256, 128 bags.
#define NROWS_MAX 262144
#define DIN 1024
#define DHID 256
#define NEG_INF_F (__int_as_float(0xff800000))

__device__ __half         g_h16[(size_t)NROWS_MAX * DHID];   // 128 MB fp16 activations
__device__ float          g_scores[NROWS_MAX];
__device__ float          g_psum[2048 * 256];
__device__ float          g_psumsq[2048 * 256];
__device__ float          g_bn_a[DHID];
__device__ float          g_bn_c[DHID];
__device__ long long      g_off[1025];
__device__ unsigned short g_Bh[(size_t)DHID * DIN];          // W1^T fp16 [256][1024]

// ---------------- helpers ----------------
__device__ __forceinline__ uint32_t smem_u32(const void* p) {
    uint32_t a;
    asm("{ .reg .u64 t; cvta.to.shared.u64 t, %1; cvt.u32.u64 %0, t; }" : "=r"(a) : "l"(p));
    return a;
}
// fp16x2 pack, memory order: first, second
__device__ __forceinline__ uint32_t pack2h(float first, float second) {
    uint32_t r;
    asm("cvt.rn.f16x2.f32 %0, %1, %2;" : "=r"(r) : "f"(second), "f"(first));
    return r;
}
__device__ __forceinline__ void ldm4(uint32_t* r, uint32_t addr) {
    asm volatile("ldmatrix.sync.aligned.m8n8.x4.shared.b16 {%0,%1,%2,%3}, [%4];"
                 : "=r"(r[0]), "=r"(r[1]), "=r"(r[2]), "=r"(r[3]) : "r"(addr));
}
__device__ __forceinline__ void mma16816h(float* c, const uint32_t* a, uint32_t b0, uint32_t b1) {
    asm volatile(
        "mma.sync.aligned.m16n8k16.row.col.f32.f16.f16.f32 "
        "{%0,%1,%2,%3}, {%4,%5,%6,%7}, {%8,%9}, {%0,%1,%2,%3};"
        : "+f"(c[0]), "+f"(c[1]), "+f"(c[2]), "+f"(c[3])
        : "r"(a[0]), "r"(a[1]), "r"(a[2]), "r"(a[3]), "r"(b0), "r"(b1));
}
#define CP_ASYNC16(dst, src) \
    asm volatile("cp.async.ca.shared.global [%0], [%1], 16;" :: "r"(dst), "l"(src) : "memory")
#define CP_COMMIT()  asm volatile("cp.async.commit_group;" ::: "memory")
#define CP_WAIT0()   asm volatile("cp.async.wait_group 0;" ::: "memory")

// ---------------------------------------------------------------------------
// Kernel 0: W1 [1024][256] fp32 -> fp16, K-major [256][1024]
// ---------------------------------------------------------------------------
__global__ __launch_bounds__(256)
void convert_w1_kernel(const float* __restrict__ W1)
{
    const int n = blockIdx.x;
    const int t = threadIdx.x;
    #pragma unroll
    for (int i = 0; i < DIN / 256; ++i) {
        int k = t + 256 * i;
        float x = W1[(size_t)k * DHID + n];
        __half hh = __float2half_rn(x);
        g_Bh[(size_t)n * DIN + k] = *(unsigned short*)&hh;
    }
}

// ---------------------------------------------------------------------------
// Kernel 1: single-term fp16 mma.sync GEMM, KC=64, full-N CTA 128x256,
// 512 threads (16 warps 4m x 4n, warp 32x64), double-buffered, fused stats.
// (Unchanged from R15 — 575us, ~83% of estimated datapath floor.)
// ---------------------------------------------------------------------------
__global__ __launch_bounds__(512, 1)
void gemm_mma_kernel(const float* __restrict__ A, const float* __restrict__ b1, int nrows)
{
    extern __shared__ __align__(16) char sm[];
    __shared__ float sbias[DHID];

    const int tid  = threadIdx.x;
    const int wid  = tid >> 5;
    const int lane = tid & 31;
    const int row0 = blockIdx.x * 128;

    const uint32_t smbase = smem_u32(sm);
    const int BUF = 49152;   // per-buffer: A 16KB @ +0, B 32KB @ +16384

    if (tid < 256) sbias[tid] = b1[tid];

    // ---- A staging: row = tid>>2 (4 threads/row), quarter q = tid&3 ----
    const int arow = tid >> 2;
    const int aq   = tid & 3;
    const float* abase = A + (size_t)(row0 + arow) * DIN + aq * 16;
    const uint32_t a_st0 = (uint32_t)arow * 128 + (((aq * 2    ) ^ (arow & 7)) << 4);
    const uint32_t a_st1 = (uint32_t)arow * 128 + (((aq * 2 + 1) ^ (arow & 7)) << 4);

    // ---- B staging (cp.async): row = tid>>1 (256 rows), half = tid&1 ----
    const int bn    = tid >> 1;
    const int bhalf = tid & 1;
    const unsigned short* bp = g_Bh + (size_t)bn * DIN + bhalf * 32;
    uint32_t b_st[4];
    #pragma unroll
    for (int j = 0; j < 4; ++j)
        b_st[j] = 16384u + (uint32_t)bn * 128 + (((bhalf * 4 + j) ^ (bn & 7)) << 4);

    // ---- stage chunk 0 ----
    {
        #pragma unroll
        for (int j = 0; j < 4; ++j) CP_ASYNC16(smbase + b_st[j], bp + j * 8);
        CP_COMMIT();
        float4 u0 = *(const float4*)(abase);
        float4 v0 = *(const float4*)(abase + 4);
        float4 u1 = *(const float4*)(abase + 8);
        float4 v1 = *(const float4*)(abase + 12);
        *(uint4*)(sm + a_st0) = make_uint4(pack2h(u0.x, u0.y), pack2h(u0.z, u0.w),
                                           pack2h(v0.x, v0.y), pack2h(v0.z, v0.w));
        *(uint4*)(sm + a_st1) = make_uint4(pack2h(u1.x, u1.y), pack2h(u1.z, u1.w),
                                           pack2h(v1.x, v1.y), pack2h(v1.z, v1.w));
        CP_WAIT0();
    }
    __syncthreads();

    // ---- warp compute mapping: 4m x 4n ----
    const int m0w  = (wid >> 2) * 32;
    const int n0w  = (wid & 3) * 64;
    const int lr   = lane & 15;
    const int lsel = (lane >> 4) & 1;

    float acc[2][8][4];
    #pragma unroll
    for (int mt = 0; mt < 2; ++mt)
        #pragma unroll
        for (int nt = 0; nt < 8; ++nt)
            #pragma unroll
            for (int q = 0; q < 4; ++q) acc[mt][nt][q] = 0.f;

    const int NKC = DIN / 64;   // 16 chunks
    for (int kc = 0; kc < NKC; ++kc) {
        const uint32_t cur = (uint32_t)(kc & 1) * BUF;
        const bool pf = (kc + 1) < NKC;
        const uint32_t nxt = (uint32_t)((kc + 1) & 1) * BUF;
        const int ko = (kc + 1) * 64;

        float4 u0, v0, u1, v1;
        if (pf) {
            #pragma unroll
            for (int j = 0; j < 4; ++j) CP_ASYNC16(smbase + nxt + b_st[j], bp + ko + j * 8);
            CP_COMMIT();
            u0 = *(const float4*)(abase + ko);
            v0 = *(const float4*)(abase + ko + 4);
            u1 = *(const float4*)(abase + ko + 8);
            v1 = *(const float4*)(abase + ko + 12);
        }

        #pragma unroll
        for (int ks = 0; ks < 4; ++ks) {
            const uint32_t ku = (uint32_t)(2 * ks + lsel);   // 0..7
            uint32_t ah[2][4];
            #pragma unroll
            for (int mt = 0; mt < 2; ++mt) {
                int r = m0w + mt * 16 + lr;
                uint32_t addr = smbase + cur + (uint32_t)r * 128 + ((ku ^ (r & 7)) << 4);
                ldm4(ah[mt], addr);
            }
            uint32_t bf[4][4];
            #pragma unroll
            for (int p = 0; p < 4; ++p) {
                int rn = n0w + p * 16 + lr;
                uint32_t addr = smbase + cur + 16384 + (uint32_t)rn * 128 + ((ku ^ (rn & 7)) << 4);
                ldm4(bf[p], addr);
            }
            #pragma unroll
            for (int p = 0; p < 4; ++p)
                #pragma unroll
                for (int mt = 0; mt < 2; ++mt) {
                    mma16816h(acc[mt][2 * p],     ah[mt], bf[p][0], bf[p][2]);
                    mma16816h(acc[mt][2 * p + 1], ah[mt], bf[p][1], bf[p][3]);
                }
        }

        if (pf) {
            *(uint4*)(sm + nxt + a_st0) = make_uint4(pack2h(u0.x, u0.y), pack2h(u0.z, u0.w),
                                                     pack2h(v0.x, v0.y), pack2h(v0.z, v0.w));
            *(uint4*)(sm + nxt + a_st1) = make_uint4(pack2h(u1.x, u1.y), pack2h(u1.z, u1.w),
                                                     pack2h(v1.x, v1.y), pack2h(v1.z, v1.w));
            CP_WAIT0();
        }
        __syncthreads();
    }

    // ---- epilogue: bias add, write h fp16, fused column sum/sumsq ----
    const int erow = lane >> 2;
    const int ecol = (lane & 3) * 2;
    float* ss = (float*)sm;                 // [16][8][4][2] = 1024 floats
    float* qq = (float*)(sm + 4096);
    #pragma unroll
    for (int nt = 0; nt < 8; ++nt) {
        int gc = n0w + nt * 8 + ecol;
        float bx = sbias[gc], by = sbias[gc + 1];
        float sx = 0.f, sy = 0.f, qx = 0.f, qy = 0.f;
        #pragma unroll
        for (int mt = 0; mt < 2; ++mt) {
            int gr0 = row0 + m0w + mt * 16 + erow;
            float2 v0 = make_float2(acc[mt][nt][0] + bx, acc[mt][nt][1] + by);
            float2 v1 = make_float2(acc[mt][nt][2] + bx, acc[mt][nt][3] + by);
            *(uint32_t*)&g_h16[(size_t)gr0 * DHID + gc]       = pack2h(v0.x, v0.y);
            *(uint32_t*)&g_h16[(size_t)(gr0 + 8) * DHID + gc] = pack2h(v1.x, v1.y);
            sx += v0.x + v1.x;  sy += v0.y + v1.y;
            qx = fmaf(v0.x, v0.x, fmaf(v1.x, v1.x, qx));
            qy = fmaf(v0.y, v0.y, fmaf(v1.y, v1.y, qy));
        }
        #pragma unroll
        for (int o = 4; o < 32; o <<= 1) {
            sx += __shfl_xor_sync(0xffffffffu, sx, o);
            sy += __shfl_xor_sync(0xffffffffu, sy, o);
            qx += __shfl_xor_sync(0xffffffffu, qx, o);
            qy += __shfl_xor_sync(0xffffffffu, qy, o);
        }
        if (lane < 4) {
            int idx = ((wid * 8 + nt) * 4 + lane) * 2;
            ss[idx] = sx;  ss[idx + 1] = sy;
            qq[idx] = qx;  qq[idx + 1] = qy;
        }
    }
    __syncthreads();
    if (tid < 256) {
        const int lc = tid;
        const int nw = lc >> 6;
        const int within = lc & 63;
        const int nt  = within >> 3;
        const int grp = (within & 7) >> 1;
        const int xy  = within & 1;
        float s = 0.f, q = 0.f;
        #pragma unroll
        for (int mw = 0; mw < 4; ++mw) {
            int wd = mw * 4 + nw;
            int idx = ((wd * 8 + nt) * 4 + grp) * 2 + xy;
            s += ss[idx];
            q += qq[idx];
        }
        g_psum[(size_t)blockIdx.x * 256 + lc]   = s;
        g_psumsq[(size_t)blockIdx.x * 256 + lc] = q;
    }
}

// ---------------------------------------------------------------------------
// Kernel 3: finalize BN coefficients (256 blocks); block 0 also computes bag
// offsets (folds the former offsets_kernel launch).
// ---------------------------------------------------------------------------
__global__ __launch_bounds__(256)
void stats_final_kernel(const float* __restrict__ gamma,
                        const float* __restrict__ beta,
                        const int* __restrict__ bag_sizes,
                        int n_bags, int nrows)
{
    __shared__ float rs[256], rq[256];
    const int c   = blockIdx.x;
    const int tid = threadIdx.x;

    if (c == 0 && tid == 0) {
        long long a = 0;
        g_off[0] = 0;
        for (int b = 0; b < n_bags; ++b) { a += (long long)bag_sizes[b]; g_off[b + 1] = a; }
    }

    float s = 0.f, q = 0.f;
    for (int y = tid; y < 2048; y += 256) {
        s += g_psum[(size_t)y * 256 + c];
        q += g_psumsq[(size_t)y * 256 + c];
    }
    rs[tid] = s; rq[tid] = q;
    __syncthreads();
    #pragma unroll
    for (int o = 128; o; o >>= 1) {
        if (tid < o) { rs[tid] += rs[tid + o]; rq[tid] += rq[tid + o]; }
        __syncthreads();
    }
    if (tid == 0) {
        float inv_n = 1.0f / (float)nrows;
        float mean  = rs[0] * inv_n;
        float var   = fmaf(-mean, mean, rq[0] * inv_n);
        float rstd  = rsqrtf(var + 1e-5f);
        float a     = gamma[c] * rstd;
        g_bn_a[c] = a;
        g_bn_c[c] = fmaf(-mean, a, beta[c]);
    }
}

// ---------------------------------------------------------------------------
// Kernel 4: scores, fp16 h. 4 rows per warp (MLP=4), REVERSED block order so
// the most recently GEMM-written rows (still L2-resident) are read first.
// ---------------------------------------------------------------------------
__global__ __launch_bounds__(256)
void scores_kernel(const float* __restrict__ W2, const float* __restrict__ b2,
                   int nrows)
{
    __shared__ float sa[DHID], sc[DHID], sw[DHID];
    const int tid = threadIdx.x;
    sa[tid] = g_bn_a[tid];
    sc[tid] = g_bn_c[tid];
    sw[tid] = W2[tid];
    __syncthreads();

    const int warp = tid >> 5;
    const int lane = tid & 31;
    const int rb   = gridDim.x - 1 - blockIdx.x;      // reversed mapping
    const int row0 = rb * 32 + warp * 4;
    if (row0 >= nrows) return;

    const int c0 = lane * 8;
    const __half* hbase = g_h16 + (size_t)row0 * DHID + c0;
    uint4 p0 = *(const uint4*)(hbase);
    uint4 p1 = *(const uint4*)(hbase + DHID);
    uint4 p2 = *(const uint4*)(hbase + 2 * DHID);
    uint4 p3 = *(const uint4*)(hbase + 3 * DHID);

    float acc0 = 0.f, acc1 = 0.f, acc2 = 0.f, acc3 = 0.f;
    const uint32_t* w0 = &p0.x;
    const uint32_t* w1 = &p1.x;
    const uint32_t* w2 = &p2.x;
    const uint32_t* w3 = &p3.x;
    #pragma unroll
    for (int j = 0; j < 4; ++j) {
        int c = c0 + 2 * j;
        float2 v0 = __half22float2(*(__half2*)&w0[j]);
        float2 v1 = __half22float2(*(__half2*)&w1[j]);
        float2 v2 = __half22float2(*(__half2*)&w2[j]);
        float2 v3 = __half22float2(*(__half2*)&w3[j]);
        float a0 = sa[c], a1 = sa[c + 1];
        float cc0 = sc[c], cc1 = sc[c + 1];
        float ww0 = sw[c], ww1 = sw[c + 1];
        acc0 += fmaxf(fmaf(a0, v0.x, cc0), 0.f) * ww0 + fmaxf(fmaf(a1, v0.y, cc1), 0.f) * ww1;
        acc1 += fmaxf(fmaf(a0, v1.x, cc0), 0.f) * ww0 + fmaxf(fmaf(a1, v1.y, cc1), 0.f) * ww1;
        acc2 += fmaxf(fmaf(a0, v2.x, cc0), 0.f) * ww0 + fmaxf(fmaf(a1, v2.y, cc1), 0.f) * ww1;
        acc3 += fmaxf(fmaf(a0, v3.x, cc0), 0.f) * ww0 + fmaxf(fmaf(a1, v3.y, cc1), 0.f) * ww1;
    }
    #pragma unroll
    for (int o = 16; o; o >>= 1) {
        acc0 += __shfl_xor_sync(0xffffffffu, acc0, o);
        acc1 += __shfl_xor_sync(0xffffffffu, acc1, o);
        acc2 += __shfl_xor_sync(0xffffffffu, acc2, o);
        acc3 += __shfl_xor_sync(0xffffffffu, acc3, o);
    }
    if (lane == 0) {
        float bb = b2[0];
        g_scores[row0]     = acc0 + bb;
        g_scores[row0 + 1] = acc1 + bb;
        g_scores[row0 + 2] = acc2 + bb;
        g_scores[row0 + 3] = acc3 + bb;
    }
}

// Kernel 6: per-bag stable softmax
__global__ __launch_bounds__(256)
void bag_softmax_kernel(float* __restrict__ out)
{
    __shared__ float red[256];
    const int b   = blockIdx.x;
    const int tid = threadIdx.x;
    const long long s = g_off[b];
    const long long e = g_off[b + 1];

    float m = NEG_INF_F;
    for (long long i = s + tid; i < e; i += 256) m = fmaxf(m, g_scores[i]);
    red[tid] = m;
    __syncthreads();
    #pragma unroll
    for (int o = 128; o; o >>= 1) {
        if (tid < o) red[tid] = fmaxf(red[tid], red[tid + o]);
        __syncthreads();
    }
    const float M = red[0];
    __syncthreads();

    float z = 0.f;
    for (long long i = s + tid; i < e; i += 256) {
        float ev = expf(g_scores[i] - M);
        out[i] = ev;
        z += ev;
    }
    red[tid] = z;
    __syncthreads();
    #pragma unroll
    for (int o = 128; o; o >>= 1) {
        if (tid < o) red[tid] += red[tid + o];
        __syncthreads();
    }
    const float inv = 1.0f / red[0];
    for (long long i = s + tid; i < e; i += 256) out[i] *= inv;
}

// ---------------------------------------------------------------------------
extern "C" void kernel_launch(void* const* d_in, const int* in_sizes, int n_in,
                              void* d_out, int out_size)
{
    const float* features  = (const float*)d_in[0];
    const int*   bag_sizes = (const int*)d_in[1];
    const float* W1        = (const float*)d_in[2];
    const float* b1        = (const float*)d_in[3];
    const float* gamma     = (const float*)d_in[4];
    const float* beta      = (const float*)d_in[5];
    const float* W2        = (const float*)d_in[6];
    const float* b2        = (const float*)d_in[7];
    float*       out       = (float*)d_out;

    const int n      = out_size;        // 262144
    const int n_bags = in_sizes[1];     // 128

    const int GEMM_SMEM = 98304;        // 2 x (16KB A + 32KB B)
    cudaFuncSetAttribute(gemm_mma_kernel,
                         cudaFuncAttributeMaxDynamicSharedMemorySize, GEMM_SMEM);

    convert_w1_kernel<<<DHID, 256>>>(W1);
    gemm_mma_kernel<<<n / 128, 512, GEMM_SMEM>>>(features, b1, n);
    stats_final_kernel<<<DHID, 256>>>(gamma, beta, bag_sizes, n_bags, n);
    scores_kernel<<<(n + 31) / 32, 256>>>(W2, b2, n);
    bag_softmax_kernel<<<n_bags, 256>>>(out);
}